// round 10
// baseline (speedup 1.0000x reference)
#include <cuda_runtime.h>
#include <cuda_bf16.h>
#include <math.h>
#include <stdint.h>

#define BB 2
#define SS 2048
#define DD 1024
#define HH 16
#define DK 64
#define MROWS (BB*SS)   // 4096

// Scratch (device globals — allocation is forbidden)
__device__ float g_qlin[MROWS*DD];
__device__ float g_klin[MROWS*DD];
__device__ float g_vlin[MROWS*DD];
__device__ float g_cos[SS*32];
__device__ float g_sin[SS*32];
// bf16-split packed operands for flash: u32 = packed bf16x2
__device__ uint32_t g_qh[BB*HH*SS*32];
__device__ uint32_t g_ql[BB*HH*SS*32];
__device__ uint32_t g_kh[BB*HH*SS*32];
__device__ uint32_t g_kl[BB*HH*SS*32];
__device__ uint32_t g_vh[BB*HH*(SS/2)*DK];
__device__ uint32_t g_vl[BB*HH*(SS/2)*DK];
// bf16-split packed operands for GEMMs
__device__ uint32_t g_ah[3][MROWS*512];
__device__ uint32_t g_al[3][MROWS*512];
__device__ uint32_t g_wh[4][DD*512];
__device__ uint32_t g_wl[4][DD*512];
__device__ uint32_t g_cth[MROWS*512];
__device__ uint32_t g_ctl[MROWS*512];

// ---------------------------------------------------------------------------
__device__ __forceinline__ uint32_t pack_hi(float a, float b, float& ra, float& rb)
{
    __nv_bfloat16 ha = __float2bfloat16(a);
    __nv_bfloat16 hb = __float2bfloat16(b);
    ra = a - __bfloat162float(ha);
    rb = b - __bfloat162float(hb);
    __nv_bfloat162 p;
    p.x = ha; p.y = hb;
    return *reinterpret_cast<uint32_t*>(&p);
}
__device__ __forceinline__ uint32_t pack_lo(float ra, float rb)
{
    __nv_bfloat162 p = __floats2bfloat162_rn(ra, rb);
    return *reinterpret_cast<uint32_t*>(&p);
}
__device__ __forceinline__ float ex2(float x)
{
    float r;
    asm("ex2.approx.f32 %0, %1;" : "=f"(r) : "f"(x));
    return r;
}

#define MMA_BF16(d, a, b) \
    asm volatile("mma.sync.aligned.m16n8k16.row.col.f32.bf16.bf16.f32 " \
        "{%0,%1,%2,%3}, {%4,%5,%6,%7}, {%8,%9}, {%0,%1,%2,%3};" \
        : "+f"(d[0]), "+f"(d[1]), "+f"(d[2]), "+f"(d[3]) \
        : "r"(a[0]), "r"(a[1]), "r"(a[2]), "r"(a[3]), "r"(b[0]), "r"(b[1]))

#define CPA16(dst, src)  asm volatile("cp.async.cg.shared.global [%0], [%1], 16;" :: "r"(dst), "l"(src))
#define CPA_COMMIT()     asm volatile("cp.async.commit_group;" ::: "memory")
#define CPA_WAIT(N)      asm volatile("cp.async.wait_group %0;" :: "n"(N) : "memory")

// ---------------------------------------------------------------------------
__global__ __launch_bounds__(256) void rope_tables(float* cosT, float* sinT)
{
    const int t = blockIdx.x * 256 + threadIdx.x;
    const int j = t & 31;
    const int s = t >> 5;
    double inv = exp(-(double)j * 0.28782313662425575);
    double sd, cd;
    sincos((double)s * inv, &sd, &cd);
    cosT[t] = (float)cd;
    sinT[t] = (float)sd;
}

// ---------------------------------------------------------------------------
__global__ __launch_bounds__(256) void split_pack3(
    const float* __restrict__ X0, const float* __restrict__ X1,
    const float* __restrict__ X2,
    uint32_t* __restrict__ Xh, uint32_t* __restrict__ Xl, size_t ostride)
{
    const float* X = (blockIdx.y == 0) ? X0 : ((blockIdx.y == 1) ? X1 : X2);
    uint32_t* H = Xh + blockIdx.y * ostride;
    uint32_t* L = Xl + blockIdx.y * ostride;
    const size_t t = (size_t)blockIdx.x * 256 + threadIdx.x;
    float4 v0 = ((const float4*)X)[2*t];
    float4 v1 = ((const float4*)X)[2*t+1];
    float r0, r1, r2, r3, r4, r5, r6, r7;
    uint4 h, l;
    h.x = pack_hi(v0.x, v0.y, r0, r1);
    h.y = pack_hi(v0.z, v0.w, r2, r3);
    h.z = pack_hi(v1.x, v1.y, r4, r5);
    h.w = pack_hi(v1.z, v1.w, r6, r7);
    l.x = pack_lo(r0, r1); l.y = pack_lo(r2, r3);
    l.z = pack_lo(r4, r5); l.w = pack_lo(r6, r7);
    ((uint4*)H)[t] = h;
    ((uint4*)L)[t] = l;
}

__global__ __launch_bounds__(256) void split_pack4(
    const float* __restrict__ X0, const float* __restrict__ X1,
    const float* __restrict__ X2, const float* __restrict__ X3,
    uint32_t* __restrict__ Xh, uint32_t* __restrict__ Xl, size_t ostride)
{
    const float* X = (blockIdx.y == 0) ? X0 : ((blockIdx.y == 1) ? X1 :
                     ((blockIdx.y == 2) ? X2 : X3));
    uint32_t* H = Xh + blockIdx.y * ostride;
    uint32_t* L = Xl + blockIdx.y * ostride;
    const size_t t = (size_t)blockIdx.x * 256 + threadIdx.x;
    float4 v0 = ((const float4*)X)[2*t];
    float4 v1 = ((const float4*)X)[2*t+1];
    float r0, r1, r2, r3, r4, r5, r6, r7;
    uint4 h, l;
    h.x = pack_hi(v0.x, v0.y, r0, r1);
    h.y = pack_hi(v0.z, v0.w, r2, r3);
    h.z = pack_hi(v1.x, v1.y, r4, r5);
    h.w = pack_hi(v1.z, v1.w, r6, r7);
    l.x = pack_lo(r0, r1); l.y = pack_lo(r2, r3);
    l.z = pack_lo(r4, r5); l.w = pack_lo(r6, r7);
    ((uint4*)H)[t] = h;
    ((uint4*)L)[t] = l;
}

// ---------------------------------------------------------------------------
// gemm_tc3: 128x128 tile, 8 warps (64x32 warp tiles), 3x-split bf16 MMA.
// Row-major pitch-12 smem ([row][k2], bank = (12*qrow+qk)%32 conflict-free),
// loaded directly by cp.async — no LDG/STS staging. 3-stage ring, 1 sync/iter.
// Stage layout (u32, base s*6144): Ah@0, Al@1536, Wh@3072, Wl@4608 (row*12+k2).
// ---------------------------------------------------------------------------
#define GPITCH 12
#define GSTG 6144                   // u32 per stage
#define GEMM_SMEM (3*GSTG*4)        // 73728 B

struct GArg {
    const uint32_t *ah, *al, *wh, *wl;
    const float* bias;
    float* c;
};

__global__ __launch_bounds__(256, 2) void gemm_tc3(GArg g0, GArg g1, GArg g2)
{
    extern __shared__ uint32_t gsm[];
    const uint32_t sbase = (uint32_t)__cvta_generic_to_shared(gsm);

    GArg g = (blockIdx.z == 0) ? g0 : ((blockIdx.z == 1) ? g1 : g2);
    const int tid = threadIdx.x;
    const int bm = blockIdx.y, bn = blockIdx.x;
    const int lane = tid & 31, wid = tid >> 5;
    const int wm = (wid >> 2) * 64;
    const int wn = (wid & 3) * 32;
    const int qrow = lane >> 2, qk = lane & 3;

    // loader: thread t handles row r of (A if sel==0 else W), hi+lo, 32B each
    const int r   = tid & 127;
    const int sel = tid >> 7;
    const uint32_t* ph0 = (sel ? g.wh + (size_t)(bn*128 + r)*512
                               : g.ah + (size_t)(bm*128 + r)*512);
    const uint32_t* pl0 = (sel ? g.wl + (size_t)(bn*128 + r)*512
                               : g.al + (size_t)(bm*128 + r)*512);
    const uint32_t dsth = sbase + (sel*3072 + r*GPITCH)*4;   // + stage*GSTG*4
    const uint32_t dstl = dsth + 1536*4;

    float d[4][4][4];
    #pragma unroll
    for (int mt = 0; mt < 4; mt++)
        #pragma unroll
        for (int nt = 0; nt < 4; nt++)
            #pragma unroll
            for (int i = 0; i < 4; i++) d[mt][nt][i] = 0.f;

    // prologue: stages 0, 1 (chunks 0, 1)
    #pragma unroll
    for (int p = 0; p < 2; p++) {
        const uint32_t sb = (uint32_t)(p*GSTG*4);
        CPA16(dsth + sb,      ph0 + p*8);
        CPA16(dsth + sb + 16, ph0 + p*8 + 4);
        CPA16(dstl + sb,      pl0 + p*8);
        CPA16(dstl + sb + 16, pl0 + p*8 + 4);
        CPA_COMMIT();
    }

    int s = 0;
    for (int c = 0; c < 64; c++) {
        if (c + 1 < 64) { CPA_WAIT(1); } else { CPA_WAIT(0); }
        __syncthreads();

        // issue load for chunk c+2 into stage (s+2)%3 (read last in iter c-1)
        if (c + 2 < 64) {
            const int s2 = (s + 2 >= 3) ? (s - 1) : (s + 2);
            const uint32_t sb = (uint32_t)(s2*GSTG*4);
            CPA16(dsth + sb,      ph0 + (c+2)*8);
            CPA16(dsth + sb + 16, ph0 + (c+2)*8 + 4);
            CPA16(dstl + sb,      pl0 + (c+2)*8);
            CPA16(dstl + sb + 16, pl0 + (c+2)*8 + 4);
            CPA_COMMIT();
        }

        const uint32_t* S = gsm + s*GSTG;

        // fragments (row-major: [row*12 + k2])
        uint32_t afh[4][4], afl[4][4], bfh[4][2], bfl[4][2];
        #pragma unroll
        for (int mt = 0; mt < 4; mt++) {
            const int m0 = wm + mt*16 + qrow;
            #pragma unroll
            for (int i = 0; i < 4; i++) {
                const int m  = m0 + ((i & 1) << 3);
                const int k2 = qk + ((i >> 1) << 2);
                afh[mt][i] = S[m*GPITCH + k2];
                afl[mt][i] = S[1536 + m*GPITCH + k2];
            }
        }
        #pragma unroll
        for (int nt = 0; nt < 4; nt++) {
            const int n0 = wn + nt*8 + qrow;
            #pragma unroll
            for (int i = 0; i < 2; i++) {
                bfh[nt][i] = S[3072 + n0*GPITCH + qk + 4*i];
                bfl[nt][i] = S[4608 + n0*GPITCH + qk + 4*i];
            }
        }

        #pragma unroll
        for (int mt = 0; mt < 4; mt++)
            #pragma unroll
            for (int nt = 0; nt < 4; nt++) {
                MMA_BF16(d[mt][nt], afh[mt], bfh[nt]);
                MMA_BF16(d[mt][nt], afh[mt], bfl[nt]);
                MMA_BF16(d[mt][nt], afl[mt], bfh[nt]);
            }

        s = (s + 1 >= 3) ? 0 : (s + 1);
    }

    #pragma unroll
    for (int mt = 0; mt < 4; mt++)
        #pragma unroll
        for (int nt = 0; nt < 4; nt++) {
            int col0 = bn*128 + wn + nt*8 + 2*qk;
            float b0 = g.bias[col0], b1 = g.bias[col0+1];
            #pragma unroll
            for (int half = 0; half < 2; half++) {
                int row = bm*128 + wm + mt*16 + qrow + 8*half;
                float2 v;
                v.x = d[mt][nt][2*half+0] + b0;
                v.y = d[mt][nt][2*half+1] + b1;
                *(float2*)&g.c[(size_t)row*DD + col0] = v;
            }
        }
}

// ---------------------------------------------------------------------------
// RoPE + head-transpose + bf16 split for Q,K. Q scale = (1/8)*log2(e).
// ---------------------------------------------------------------------------
__global__ __launch_bounds__(256) void rope_split(
    const float* __restrict__ qlin, const float* __restrict__ klin,
    const float* __restrict__ cosT, const float* __restrict__ sinT,
    uint32_t* __restrict__ qh, uint32_t* __restrict__ ql,
    uint32_t* __restrict__ kh, uint32_t* __restrict__ kl)
{
    const int t = blockIdx.x * 256 + threadIdx.x;
    const float* src = blockIdx.y ? klin : qlin;
    uint32_t* dh = blockIdx.y ? kh : qh;
    uint32_t* dl = blockIdx.y ? kl : ql;
    const float scale = blockIdx.y ? 1.0f : 0.18033688011112042f;  // 0.125*log2(e)

    const int k2 = t & 15;
    const int s  = (t >> 4) & (SS - 1);
    const int bh = t >> 15;
    const int b = bh >> 4, h = bh & 15;
    const int j0 = 2*k2, j1 = 2*k2 + 1;

    const float* sp = src + ((size_t)(b*SS + s))*DD + h*DK;
    float x0 = sp[j0],      x1 = sp[j1];
    float y0 = sp[j0 + 32], y1 = sp[j1 + 32];
    float c0 = cosT[s*32 + j0], c1 = cosT[s*32 + j1];
    float s0 = sinT[s*32 + j0], s1 = sinT[s*32 + j1];

    float o0 = (x0*c0 - y0*s0) * scale;
    float o1 = (x1*c1 - y1*s1) * scale;
    float p0 = (y0*c0 + x0*s0) * scale;
    float p1 = (y1*c1 + x1*s1) * scale;

    size_t base = ((size_t)bh*SS + s)*32;
    float r0, r1;
    uint32_t hv = pack_hi(o0, o1, r0, r1);
    dh[base + k2] = hv;            dl[base + k2] = pack_lo(r0, r1);
    hv = pack_hi(p0, p1, r0, r1);
    dh[base + k2 + 16] = hv;       dl[base + k2 + 16] = pack_lo(r0, r1);
}

// ---------------------------------------------------------------------------
__global__ __launch_bounds__(256) void v_split(
    const float* __restrict__ vlin,
    uint32_t* __restrict__ vh, uint32_t* __restrict__ vl)
{
    const int t = blockIdx.x * 256 + threadIdx.x;
    const int d4 = (t & 15) * 4;
    const int kp = (t >> 4) & 1023;
    const int bh = t >> 14;
    const int b = bh >> 4, h = bh & 15;

    const float* r0p = vlin + ((size_t)(b*SS + 2*kp))*DD + h*DK + d4;
    float4 a = *(const float4*)r0p;
    float4 c = *(const float4*)(r0p + DD);

    uint32_t hh[4], ll[4];
    float ra, rb;
    hh[0] = pack_hi(a.x, c.x, ra, rb); ll[0] = pack_lo(ra, rb);
    hh[1] = pack_hi(a.y, c.y, ra, rb); ll[1] = pack_lo(ra, rb);
    hh[2] = pack_hi(a.z, c.z, ra, rb); ll[2] = pack_lo(ra, rb);
    hh[3] = pack_hi(a.w, c.w, ra, rb); ll[3] = pack_lo(ra, rb);

    size_t base = ((size_t)bh*1024 + kp)*64 + d4;
    *(uint4*)&vh[base] = make_uint4(hh[0], hh[1], hh[2], hh[3]);
    *(uint4*)&vl[base] = make_uint4(ll[0], ll[1], ll[2], ll[3]);
}

// ---------------------------------------------------------------------------
// Flash v4 (unchanged from R9): no-max softmax, cp.async double-buffered K/V.
// ---------------------------------------------------------------------------
#define QP 36
#define VP 72
#define FLASH_SMEM (27648*4)

__global__ __launch_bounds__(256, 2) void flash_tc4(
    const uint32_t* __restrict__ qh_g, const uint32_t* __restrict__ ql_g,
    const uint32_t* __restrict__ kh_g, const uint32_t* __restrict__ kl_g,
    const uint32_t* __restrict__ vh_g, const uint32_t* __restrict__ vl_g,
    uint32_t* __restrict__ cth, uint32_t* __restrict__ ctl)
{
    extern __shared__ uint32_t smu[];
    const uint32_t sbase = (uint32_t)__cvta_generic_to_shared(smu);

    const int tid = threadIdx.x;
    const int qi = 15 - blockIdx.x;
    const int bh = blockIdx.y;
    const int b = bh >> 4, h = bh & 15;
    const int lane = tid & 31, wid = tid >> 5;
    const int qk = lane & 3, qrow = lane >> 2;
    const int wr = wid * 16;
    const int nkt = 2*qi + 2;

    const int krow = tid >> 2, kk2b = (tid & 3) * 8;
    const int vkp  = tid >> 3, vdb  = (tid & 7) * 8;
    const size_t kgo = ((size_t)bh*SS + krow)*32 + kk2b;
    const size_t vgo = ((size_t)bh*1024 + vkp)*64 + vdb;

    {
        const int row = tid >> 1, cb = (tid & 1) * 16;
        const uint32_t* sh = qh_g + ((size_t)bh*SS + qi*128 + row)*32 + cb;
        const uint32_t* sl = ql_g + ((size_t)bh*SS + qi*128 + row)*32 + cb;
        uint32_t dh = sbase + (row*QP + cb)*4;
        uint32_t dl = sbase + (4608 + row*QP + cb)*4;
        CPA16(dh,    sh);     CPA16(dh+16, sh+4);
        CPA16(dh+32, sh+8);   CPA16(dh+48, sh+12);
        CPA16(dl,    sl);     CPA16(dl+16, sl+4);
        CPA16(dl+32, sl+8);   CPA16(dl+48, sl+12);
    }
    CPA_COMMIT();

    #pragma unroll
    for (int pk = 0; pk < 2; pk++) {
        uint32_t kh_d = sbase + (9216  + pk*2304 + krow*QP + kk2b)*4;
        uint32_t kl_d = sbase + (13824 + pk*2304 + krow*QP + kk2b)*4;
        uint32_t vh_d = sbase + (18432 + pk*2304 + vkp*VP + vdb)*4;
        uint32_t vl_d = sbase + (23040 + pk*2304 + vkp*VP + vdb)*4;
        const uint32_t* skh = kh_g + kgo + (size_t)pk*64*32;
        const uint32_t* skl = kl_g + kgo + (size_t)pk*64*32;
        const uint32_t* svh = vh_g + vgo + (size_t)pk*32*64;
        const uint32_t* svl = vl_g + vgo + (size_t)pk*32*64;
        CPA16(kh_d, skh);  CPA16(kh_d+16, skh+4);
        CPA16(kl_d, skl);  CPA16(kl_d+16, skl+4);
        CPA16(vh_d, svh);  CPA16(vh_d+16, svh+4);
        CPA16(vl_d, svl);  CPA16(vl_d+16, svl+4);
        CPA_COMMIT();
    }

    float l0 = 0.f, l1 = 0.f;
    float of[8][4];
    #pragma unroll
    for (int nt = 0; nt < 8; nt++)
        #pragma unroll
        for (int i = 0; i < 4; i++) of[nt][i] = 0.f;

    const uint32_t* QhS = smu;
    const uint32_t* QlS = smu + 4608;

    for (int kt = 0; kt < nkt; kt++) {
        const int st = kt & 1;
        if (kt + 1 < nkt) { CPA_WAIT(1); } else { CPA_WAIT(0); }
        __syncthreads();

        const uint32_t* KhS = smu + 9216  + st*2304;
        const uint32_t* KlS = smu + 13824 + st*2304;
        const uint32_t* VhS = smu + 18432 + st*2304;
        const uint32_t* VlS = smu + 23040 + st*2304;

        float sf[8][4];
        #pragma unroll
        for (int nt = 0; nt < 8; nt++)
            #pragma unroll
            for (int i = 0; i < 4; i++) sf[nt][i] = 0.f;

        #pragma unroll
        for (int kc = 0; kc < 4; kc++) {
            uint32_t ah[4], al[4];
            const int k2a = qk + 8*kc, k2c = k2a + 4;
            const int r0o = (wr + qrow)*QP, r1o = (wr + qrow + 8)*QP;
            ah[0] = QhS[r0o + k2a]; ah[1] = QhS[r1o + k2a];
            ah[2] = QhS[r0o + k2c]; ah[3] = QhS[r1o + k2c];
            al[0] = QlS[r0o + k2a]; al[1] = QlS[r1o + k2a];
            al[2] = QlS[r0o + k2c]; al[3] = QlS[r1o + k2c];
            #pragma unroll
            for (int nt = 0; nt < 8; nt++) {
                const int co = (nt*8 + qrow)*QP;
                uint32_t bhh[2] = { KhS[co + k2a], KhS[co + k2c] };
                uint32_t bll[2] = { KlS[co + k2a], KlS[co + k2c] };
                MMA_BF16(sf[nt], ah, bhh);
                MMA_BF16(sf[nt], ah, bll);
                MMA_BF16(sf[nt], al, bhh);
            }
        }

        if (kt >= 2*qi) {
            #pragma unroll
            for (int nt = 0; nt < 8; nt++) {
                #pragma unroll
                for (int i = 0; i < 4; i++) {
                    int col_g = kt*64 + nt*8 + 2*qk + (i & 1);
                    int row_g = qi*128 + wr + qrow + 8*(i >> 1);
                    if (col_g > row_g) sf[nt][i] = -1e30f;
                }
            }
        }

        #pragma unroll
        for (int nt = 0; nt < 8; nt++) {
            sf[nt][0] = ex2(sf[nt][0]);
            sf[nt][1] = ex2(sf[nt][1]);
            sf[nt][2] = ex2(sf[nt][2]);
            sf[nt][3] = ex2(sf[nt][3]);
            l0 += sf[nt][0] + sf[nt][1];
            l1 += sf[nt][2] + sf[nt][3];
        }

        #pragma unroll
        for (int kc = 0; kc < 4; kc++) {
            uint32_t pah[4], pal[4];
            float r0, r1;
            pah[0] = pack_hi(sf[2*kc][0],   sf[2*kc][1],   r0, r1); pal[0] = pack_lo(r0, r1);
            pah[1] = pack_hi(sf[2*kc][2],   sf[2*kc][3],   r0, r1); pal[1] = pack_lo(r0, r1);
            pah[2] = pack_hi(sf[2*kc+1][0], sf[2*kc+1][1], r0, r1); pal[2] = pack_lo(r0, r1);
            pah[3] = pack_hi(sf[2*kc+1][2], sf[2*kc+1][3], r0, r1); pal[3] = pack_lo(r0, r1);
            const int kpa = 8*kc + qk, kpc = kpa + 4;
            #pragma unroll
            for (int nt = 0; nt < 8; nt++) {
                const int col = nt*8 + qrow;
                uint32_t bvh[2] = { VhS[kpa*VP + col], VhS[kpc*VP + col] };
                uint32_t bvl[2] = { VlS[kpa*VP + col], VlS[kpc*VP + col] };
                MMA_BF16(of[nt], pah, bvh);
                MMA_BF16(of[nt], pah, bvl);
                MMA_BF16(of[nt], pal, bvh);
            }
        }

        __syncthreads();

        if (kt + 2 < nkt) {
            const int nk = kt + 2;
            uint32_t kh_d = sbase + (9216  + st*2304 + krow*QP + kk2b)*4;
            uint32_t kl_d = sbase + (13824 + st*2304 + krow*QP + kk2b)*4;
            uint32_t vh_d = sbase + (18432 + st*2304 + vkp*VP + vdb)*4;
            uint32_t vl_d = sbase + (23040 + st*2304 + vkp*VP + vdb)*4;
            const uint32_t* skh = kh_g + kgo + (size_t)nk*64*32;
            const uint32_t* skl = kl_g + kgo + (size_t)nk*64*32;
            const uint32_t* svh = vh_g + vgo + (size_t)nk*32*64;
            const uint32_t* svl = vl_g + vgo + (size_t)nk*32*64;
            CPA16(kh_d, skh);  CPA16(kh_d+16, skh+4);
            CPA16(kl_d, skl);  CPA16(kl_d+16, skl+4);
            CPA16(vh_d, svh);  CPA16(vh_d+16, svh+4);
            CPA16(vl_d, svl);  CPA16(vl_d+16, svl+4);
            CPA_COMMIT();
        }
    }

    l0 += __shfl_xor_sync(0xffffffffu, l0, 1);
    l0 += __shfl_xor_sync(0xffffffffu, l0, 2);
    l1 += __shfl_xor_sync(0xffffffffu, l1, 1);
    l1 += __shfl_xor_sync(0xffffffffu, l1, 2);

    float inv0 = 1.f / l0, inv1 = 1.f / l1;
    #pragma unroll
    for (int nt = 0; nt < 8; nt++) {
        const int k2g = h*32 + nt*4 + qk;
        const int row0 = b*SS + qi*128 + wr + qrow;
        float r0, r1;
        uint32_t hv = pack_hi(of[nt][0]*inv0, of[nt][1]*inv0, r0, r1);
        cth[(size_t)row0*512 + k2g] = hv;
        ctl[(size_t)row0*512 + k2g] = pack_lo(r0, r1);
        hv = pack_hi(of[nt][2]*inv1, of[nt][3]*inv1, r0, r1);
        cth[(size_t)(row0+8)*512 + k2g] = hv;
        ctl[(size_t)(row0+8)*512 + k2g] = pack_lo(r0, r1);
    }
}

// ---------------------------------------------------------------------------
extern "C" void kernel_launch(void* const* d_in, const int* in_sizes, int n_in,
                              void* d_out, int out_size)
{
    (void)in_sizes; (void)n_in; (void)out_size;
    const float* query = (const float*)d_in[0];
    const float* key   = (const float*)d_in[1];
    const float* value = (const float*)d_in[2];
    const float* Wq = (const float*)d_in[4];
    const float* bq = (const float*)d_in[5];
    const float* Wk = (const float*)d_in[6];
    const float* bk = (const float*)d_in[7];
    const float* Wv = (const float*)d_in[8];
    const float* bv = (const float*)d_in[9];
    const float* Wo = (const float*)d_in[10];
    const float* bo = (const float*)d_in[11];
    float* out = (float*)d_out;

    float *qlin, *klin, *vlin, *cosT, *sinT;
    uint32_t *qh, *ql, *kh, *kl, *vh, *vl;
    uint32_t *ah, *al, *wh, *wl, *cth, *ctl;
    cudaGetSymbolAddress((void**)&qlin, g_qlin);
    cudaGetSymbolAddress((void**)&klin, g_klin);
    cudaGetSymbolAddress((void**)&vlin, g_vlin);
    cudaGetSymbolAddress((void**)&cosT, g_cos);
    cudaGetSymbolAddress((void**)&sinT, g_sin);
    cudaGetSymbolAddress((void**)&qh, g_qh);
    cudaGetSymbolAddress((void**)&ql, g_ql);
    cudaGetSymbolAddress((void**)&kh, g_kh);
    cudaGetSymbolAddress((void**)&kl, g_kl);
    cudaGetSymbolAddress((void**)&vh, g_vh);
    cudaGetSymbolAddress((void**)&vl, g_vl);
    cudaGetSymbolAddress((void**)&ah, g_ah);
    cudaGetSymbolAddress((void**)&al, g_al);
    cudaGetSymbolAddress((void**)&wh, g_wh);
    cudaGetSymbolAddress((void**)&wl, g_wl);
    cudaGetSymbolAddress((void**)&cth, g_cth);
    cudaGetSymbolAddress((void**)&ctl, g_ctl);

    const size_t ASTRIDE = (size_t)MROWS*512;
    const size_t WSTRIDE = (size_t)DD*512;

    cudaFuncSetAttribute(flash_tc4, cudaFuncAttributeMaxDynamicSharedMemorySize, FLASH_SMEM);
    cudaFuncSetAttribute(gemm_tc3,  cudaFuncAttributeMaxDynamicSharedMemorySize, GEMM_SMEM);

    rope_tables<<<SS*32/256, 256>>>(cosT, sinT);

    const int ABLK = MROWS*DD/8/256;   // 2048
    const int WBLK = DD*DD/8/256;      // 512
    dim3 sp3Grid(ABLK, 3);
    split_pack3<<<sp3Grid, 256>>>(query, key, value, ah, al, ASTRIDE);
    dim3 sp4Grid(WBLK, 4);
    split_pack4<<<sp4Grid, 256>>>(Wq, Wk, Wv, Wo, wh, wl, WSTRIDE);

    GArg gq = { ah + 0*ASTRIDE, al + 0*ASTRIDE, wh + 0*WSTRIDE, wl + 0*WSTRIDE, bq, qlin };
    GArg gk = { ah + 1*ASTRIDE, al + 1*ASTRIDE, wh + 1*WSTRIDE, wl + 1*WSTRIDE, bk, klin };
    GArg gv = { ah + 2*ASTRIDE, al + 2*ASTRIDE, wh + 2*WSTRIDE, wl + 2*WSTRIDE, bv, vlin };
    dim3 gemmGrid(DD/128, MROWS/128, 3);
    gemm_tc3<<<gemmGrid, 256, GEMM_SMEM>>>(gq, gk, gv);

    dim3 rsGrid((BB*HH*SS*16)/256, 2);
    rope_split<<<rsGrid, 256>>>(qlin, klin, cosT, sinT, qh, ql, kh, kl);
    v_split<<<(BB*HH*1024*16)/256, 256>>>(vlin, vh, vl);

    dim3 faGrid(SS/128, BB*HH);            // (16, 32)
    flash_tc4<<<faGrid, 256, FLASH_SMEM>>>(qh, ql, kh, kl, vh, vl, cth, ctl);

    GArg go = { cth, ctl, wh + 3*WSTRIDE, wl + 3*WSTRIDE, bo, out };
    dim3 gemmGridO(DD/128, MROWS/128, 1);
    gemm_tc3<<<gemmGridO, 256, GEMM_SMEM>>>(go, go, go);
}

// round 11
// speedup vs baseline: 1.1146x; 1.1146x over previous
#include <cuda_runtime.h>
#include <cuda_bf16.h>
#include <math.h>
#include <stdint.h>

#define BB 2
#define SS 2048
#define DD 1024
#define HH 16
#define DK 64
#define MROWS (BB*SS)   // 4096

// Scratch (device globals — allocation is forbidden)
__device__ float g_qlin[MROWS*DD];
__device__ float g_klin[MROWS*DD];
__device__ float g_vlin[MROWS*DD];
__device__ float g_cos[SS*32];
__device__ float g_sin[SS*32];
// bf16-split packed operands for flash: u32 = packed bf16x2
__device__ uint32_t g_qh[BB*HH*SS*32];
__device__ uint32_t g_ql[BB*HH*SS*32];
__device__ uint32_t g_kh[BB*HH*SS*32];
__device__ uint32_t g_kl[BB*HH*SS*32];
__device__ uint32_t g_vh[BB*HH*(SS/2)*DK];
__device__ uint32_t g_vl[BB*HH*(SS/2)*DK];
// bf16-split packed operands for GEMMs
__device__ uint32_t g_ah[3][MROWS*512];
__device__ uint32_t g_al[3][MROWS*512];
__device__ uint32_t g_wh[4][DD*512];
__device__ uint32_t g_wl[4][DD*512];
__device__ uint32_t g_cth[MROWS*512];
__device__ uint32_t g_ctl[MROWS*512];

// ---------------------------------------------------------------------------
__device__ __forceinline__ uint32_t pack_hi(float a, float b, float& ra, float& rb)
{
    __nv_bfloat16 ha = __float2bfloat16(a);
    __nv_bfloat16 hb = __float2bfloat16(b);
    ra = a - __bfloat162float(ha);
    rb = b - __bfloat162float(hb);
    __nv_bfloat162 p;
    p.x = ha; p.y = hb;
    return *reinterpret_cast<uint32_t*>(&p);
}
__device__ __forceinline__ uint32_t pack_lo(float ra, float rb)
{
    __nv_bfloat162 p = __floats2bfloat162_rn(ra, rb);
    return *reinterpret_cast<uint32_t*>(&p);
}
__device__ __forceinline__ float ex2(float x)
{
    float r;
    asm("ex2.approx.f32 %0, %1;" : "=f"(r) : "f"(x));
    return r;
}

#define MMA_BF16(d, a, b) \
    asm volatile("mma.sync.aligned.m16n8k16.row.col.f32.bf16.bf16.f32 " \
        "{%0,%1,%2,%3}, {%4,%5,%6,%7}, {%8,%9}, {%0,%1,%2,%3};" \
        : "+f"(d[0]), "+f"(d[1]), "+f"(d[2]), "+f"(d[3]) \
        : "r"(a[0]), "r"(a[1]), "r"(a[2]), "r"(a[3]), "r"(b[0]), "r"(b[1]))

#define CPA16(dst, src)  asm volatile("cp.async.cg.shared.global [%0], [%1], 16;" :: "r"(dst), "l"(src))
#define CPA_COMMIT()     asm volatile("cp.async.commit_group;" ::: "memory")
#define CPA_WAIT(N)      asm volatile("cp.async.wait_group %0;" :: "n"(N) : "memory")

// ---------------------------------------------------------------------------
__global__ __launch_bounds__(256) void rope_tables(float* cosT, float* sinT)
{
    const int t = blockIdx.x * 256 + threadIdx.x;
    const int j = t & 31;
    const int s = t >> 5;
    double inv = exp(-(double)j * 0.28782313662425575);
    double sd, cd;
    sincos((double)s * inv, &sd, &cd);
    cosT[t] = (float)cd;
    sinT[t] = (float)sd;
}

// ---------------------------------------------------------------------------
__global__ __launch_bounds__(256) void split_pack3(
    const float* __restrict__ X0, const float* __restrict__ X1,
    const float* __restrict__ X2,
    uint32_t* __restrict__ Xh, uint32_t* __restrict__ Xl, size_t ostride)
{
    const float* X = (blockIdx.y == 0) ? X0 : ((blockIdx.y == 1) ? X1 : X2);
    uint32_t* H = Xh + blockIdx.y * ostride;
    uint32_t* L = Xl + blockIdx.y * ostride;
    const size_t t = (size_t)blockIdx.x * 256 + threadIdx.x;
    float4 v0 = ((const float4*)X)[2*t];
    float4 v1 = ((const float4*)X)[2*t+1];
    float r0, r1, r2, r3, r4, r5, r6, r7;
    uint4 h, l;
    h.x = pack_hi(v0.x, v0.y, r0, r1);
    h.y = pack_hi(v0.z, v0.w, r2, r3);
    h.z = pack_hi(v1.x, v1.y, r4, r5);
    h.w = pack_hi(v1.z, v1.w, r6, r7);
    l.x = pack_lo(r0, r1); l.y = pack_lo(r2, r3);
    l.z = pack_lo(r4, r5); l.w = pack_lo(r6, r7);
    ((uint4*)H)[t] = h;
    ((uint4*)L)[t] = l;
}

__global__ __launch_bounds__(256) void split_pack4(
    const float* __restrict__ X0, const float* __restrict__ X1,
    const float* __restrict__ X2, const float* __restrict__ X3,
    uint32_t* __restrict__ Xh, uint32_t* __restrict__ Xl, size_t ostride)
{
    const float* X = (blockIdx.y == 0) ? X0 : ((blockIdx.y == 1) ? X1 :
                     ((blockIdx.y == 2) ? X2 : X3));
    uint32_t* H = Xh + blockIdx.y * ostride;
    uint32_t* L = Xl + blockIdx.y * ostride;
    const size_t t = (size_t)blockIdx.x * 256 + threadIdx.x;
    float4 v0 = ((const float4*)X)[2*t];
    float4 v1 = ((const float4*)X)[2*t+1];
    float r0, r1, r2, r3, r4, r5, r6, r7;
    uint4 h, l;
    h.x = pack_hi(v0.x, v0.y, r0, r1);
    h.y = pack_hi(v0.z, v0.w, r2, r3);
    h.z = pack_hi(v1.x, v1.y, r4, r5);
    h.w = pack_hi(v1.z, v1.w, r6, r7);
    l.x = pack_lo(r0, r1); l.y = pack_lo(r2, r3);
    l.z = pack_lo(r4, r5); l.w = pack_lo(r6, r7);
    ((uint4*)H)[t] = h;
    ((uint4*)L)[t] = l;
}

// ---------------------------------------------------------------------------
// Tensor-core GEMM from pre-split bf16 hi/lo, double-buffered (R5-R9 proven,
// LDG path: operands are L1/L2-resident across CTAs — do NOT cp.async here).
// MMA emission is PASS-MAJOR: dependent writes to the same accumulator are
// 16 instructions apart instead of back-to-back (HMMA RAW latency hiding).
// ---------------------------------------------------------------------------
#define GP 136

struct GArg {
    const uint32_t *ah, *al, *wh, *wl;
    const float* bias;
    float* c;
};

__global__ __launch_bounds__(256, 2) void gemm_tc2(GArg g0, GArg g1, GArg g2)
{
    GArg g = (blockIdx.z == 0) ? g0 : ((blockIdx.z == 1) ? g1 : g2);
    __shared__ uint32_t Ah[2][8][GP], Al[2][8][GP], Wh[2][8][GP], Wl[2][8][GP];

    const int tid = threadIdx.x;
    const int bm = blockIdx.y, bn = blockIdx.x;
    const int lane = tid & 31, wid = tid >> 5;
    const int wm = (wid >> 2) * 64;
    const int wn = (wid & 3) * 32;
    const int qrow = lane >> 2, qk = lane & 3;

    const int r = tid >> 1;
    const int k2b = (tid & 1) * 4;

    const uint32_t* AhG = g.ah + ((size_t)(bm*128 + r))*512 + k2b;
    const uint32_t* AlG = g.al + ((size_t)(bm*128 + r))*512 + k2b;
    const uint32_t* WhG = g.wh + ((size_t)(bn*128 + r))*512 + k2b;
    const uint32_t* WlG = g.wl + ((size_t)(bn*128 + r))*512 + k2b;

    float d[4][4][4];
    #pragma unroll
    for (int mt = 0; mt < 4; mt++)
        #pragma unroll
        for (int nt = 0; nt < 4; nt++)
            #pragma unroll
            for (int i = 0; i < 4; i++) d[mt][nt][i] = 0.f;

    {
        uint4 a = *(const uint4*)AhG;
        uint4 b = *(const uint4*)AlG;
        uint4 c = *(const uint4*)WhG;
        uint4 e = *(const uint4*)WlG;
        Ah[0][k2b+0][r] = a.x; Ah[0][k2b+1][r] = a.y; Ah[0][k2b+2][r] = a.z; Ah[0][k2b+3][r] = a.w;
        Al[0][k2b+0][r] = b.x; Al[0][k2b+1][r] = b.y; Al[0][k2b+2][r] = b.z; Al[0][k2b+3][r] = b.w;
        Wh[0][k2b+0][r] = c.x; Wh[0][k2b+1][r] = c.y; Wh[0][k2b+2][r] = c.z; Wh[0][k2b+3][r] = c.w;
        Wl[0][k2b+0][r] = e.x; Wl[0][k2b+1][r] = e.y; Wl[0][k2b+2][r] = e.z; Wl[0][k2b+3][r] = e.w;
    }
    __syncthreads();

    int st = 0;
    for (int k2o = 8; k2o <= 512; k2o += 8) {
        uint4 na, nb, nc, ne;
        const bool has = (k2o < 512);
        if (has) {
            na = *(const uint4*)(AhG + k2o);
            nb = *(const uint4*)(AlG + k2o);
            nc = *(const uint4*)(WhG + k2o);
            ne = *(const uint4*)(WlG + k2o);
        }

        uint32_t afh[4][4], afl[4][4], bfh[4][2], bfl[4][2];
        #pragma unroll
        for (int mt = 0; mt < 4; mt++) {
            int m0 = wm + mt*16 + qrow;
            #pragma unroll
            for (int i = 0; i < 4; i++) {
                int m  = m0 + ((i & 1) << 3);
                int k2 = qk + ((i >> 1) << 2);
                afh[mt][i] = Ah[st][k2][m];
                afl[mt][i] = Al[st][k2][m];
            }
        }
        #pragma unroll
        for (int nt = 0; nt < 4; nt++) {
            int n0 = wn + nt*8 + qrow;
            #pragma unroll
            for (int i = 0; i < 2; i++) {
                bfh[nt][i] = Wh[st][qk + 4*i][n0];
                bfl[nt][i] = Wl[st][qk + 4*i][n0];
            }
        }

        // pass-major: 16 independent MMAs between dependent accumulator writes
        #pragma unroll
        for (int mt = 0; mt < 4; mt++)
            #pragma unroll
            for (int nt = 0; nt < 4; nt++)
                MMA_BF16(d[mt][nt], afh[mt], bfh[nt]);
        #pragma unroll
        for (int mt = 0; mt < 4; mt++)
            #pragma unroll
            for (int nt = 0; nt < 4; nt++)
                MMA_BF16(d[mt][nt], afh[mt], bfl[nt]);
        #pragma unroll
        for (int mt = 0; mt < 4; mt++)
            #pragma unroll
            for (int nt = 0; nt < 4; nt++)
                MMA_BF16(d[mt][nt], afl[mt], bfh[nt]);

        if (has) {
            int s2 = st ^ 1;
            Ah[s2][k2b+0][r] = na.x; Ah[s2][k2b+1][r] = na.y; Ah[s2][k2b+2][r] = na.z; Ah[s2][k2b+3][r] = na.w;
            Al[s2][k2b+0][r] = nb.x; Al[s2][k2b+1][r] = nb.y; Al[s2][k2b+2][r] = nb.z; Al[s2][k2b+3][r] = nb.w;
            Wh[s2][k2b+0][r] = nc.x; Wh[s2][k2b+1][r] = nc.y; Wh[s2][k2b+2][r] = nc.z; Wh[s2][k2b+3][r] = nc.w;
            Wl[s2][k2b+0][r] = ne.x; Wl[s2][k2b+1][r] = ne.y; Wl[s2][k2b+2][r] = ne.z; Wl[s2][k2b+3][r] = ne.w;
        }
        __syncthreads();
        st ^= 1;
    }

    #pragma unroll
    for (int mt = 0; mt < 4; mt++)
        #pragma unroll
        for (int nt = 0; nt < 4; nt++) {
            int col0 = bn*128 + wn + nt*8 + 2*qk;
            float b0 = g.bias[col0], b1 = g.bias[col0+1];
            #pragma unroll
            for (int half = 0; half < 2; half++) {
                int row = bm*128 + wm + mt*16 + qrow + 8*half;
                float2 v;
                v.x = d[mt][nt][2*half+0] + b0;
                v.y = d[mt][nt][2*half+1] + b1;
                *(float2*)&g.c[(size_t)row*DD + col0] = v;
            }
        }
}

// ---------------------------------------------------------------------------
// RoPE + head-transpose + bf16 split for Q,K. Q scale = (1/8)*log2(e).
// ---------------------------------------------------------------------------
__global__ __launch_bounds__(256) void rope_split(
    const float* __restrict__ qlin, const float* __restrict__ klin,
    const float* __restrict__ cosT, const float* __restrict__ sinT,
    uint32_t* __restrict__ qh, uint32_t* __restrict__ ql,
    uint32_t* __restrict__ kh, uint32_t* __restrict__ kl)
{
    const int t = blockIdx.x * 256 + threadIdx.x;
    const float* src = blockIdx.y ? klin : qlin;
    uint32_t* dh = blockIdx.y ? kh : qh;
    uint32_t* dl = blockIdx.y ? kl : ql;
    const float scale = blockIdx.y ? 1.0f : 0.18033688011112042f;  // 0.125*log2(e)

    const int k2 = t & 15;
    const int s  = (t >> 4) & (SS - 1);
    const int bh = t >> 15;
    const int b = bh >> 4, h = bh & 15;
    const int j0 = 2*k2, j1 = 2*k2 + 1;

    const float* sp = src + ((size_t)(b*SS + s))*DD + h*DK;
    float x0 = sp[j0],      x1 = sp[j1];
    float y0 = sp[j0 + 32], y1 = sp[j1 + 32];
    float c0 = cosT[s*32 + j0], c1 = cosT[s*32 + j1];
    float s0 = sinT[s*32 + j0], s1 = sinT[s*32 + j1];

    float o0 = (x0*c0 - y0*s0) * scale;
    float o1 = (x1*c1 - y1*s1) * scale;
    float p0 = (y0*c0 + x0*s0) * scale;
    float p1 = (y1*c1 + x1*s1) * scale;

    size_t base = ((size_t)bh*SS + s)*32;
    float r0, r1;
    uint32_t hv = pack_hi(o0, o1, r0, r1);
    dh[base + k2] = hv;            dl[base + k2] = pack_lo(r0, r1);
    hv = pack_hi(p0, p1, r0, r1);
    dh[base + k2 + 16] = hv;       dl[base + k2 + 16] = pack_lo(r0, r1);
}

// ---------------------------------------------------------------------------
__global__ __launch_bounds__(256) void v_split(
    const float* __restrict__ vlin,
    uint32_t* __restrict__ vh, uint32_t* __restrict__ vl)
{
    const int t = blockIdx.x * 256 + threadIdx.x;
    const int d4 = (t & 15) * 4;
    const int kp = (t >> 4) & 1023;
    const int bh = t >> 14;
    const int b = bh >> 4, h = bh & 15;

    const float* r0p = vlin + ((size_t)(b*SS + 2*kp))*DD + h*DK + d4;
    float4 a = *(const float4*)r0p;
    float4 c = *(const float4*)(r0p + DD);

    uint32_t hh[4], ll[4];
    float ra, rb;
    hh[0] = pack_hi(a.x, c.x, ra, rb); ll[0] = pack_lo(ra, rb);
    hh[1] = pack_hi(a.y, c.y, ra, rb); ll[1] = pack_lo(ra, rb);
    hh[2] = pack_hi(a.z, c.z, ra, rb); ll[2] = pack_lo(ra, rb);
    hh[3] = pack_hi(a.w, c.w, ra, rb); ll[3] = pack_lo(ra, rb);

    size_t base = ((size_t)bh*1024 + kp)*64 + d4;
    *(uint4*)&vh[base] = make_uint4(hh[0], hh[1], hh[2], hh[3]);
    *(uint4*)&vl[base] = make_uint4(ll[0], ll[1], ll[2], ll[3]);
}

// ---------------------------------------------------------------------------
// Flash v5 = v4 (no-max softmax, cp.async double-buffered K/V) with MMA
// emission reordered pass-major: dependent accumulator writes are 8 MMAs
// apart instead of back-to-back.
// ---------------------------------------------------------------------------
#define QP 36
#define VP 72
#define FLASH_SMEM (27648*4)

__global__ __launch_bounds__(256, 2) void flash_tc5(
    const uint32_t* __restrict__ qh_g, const uint32_t* __restrict__ ql_g,
    const uint32_t* __restrict__ kh_g, const uint32_t* __restrict__ kl_g,
    const uint32_t* __restrict__ vh_g, const uint32_t* __restrict__ vl_g,
    uint32_t* __restrict__ cth, uint32_t* __restrict__ ctl)
{
    extern __shared__ uint32_t smu[];
    const uint32_t sbase = (uint32_t)__cvta_generic_to_shared(smu);

    const int tid = threadIdx.x;
    const int qi = 15 - blockIdx.x;
    const int bh = blockIdx.y;
    const int b = bh >> 4, h = bh & 15;
    const int lane = tid & 31, wid = tid >> 5;
    const int qk = lane & 3, qrow = lane >> 2;
    const int wr = wid * 16;
    const int nkt = 2*qi + 2;

    const int krow = tid >> 2, kk2b = (tid & 3) * 8;
    const int vkp  = tid >> 3, vdb  = (tid & 7) * 8;
    const size_t kgo = ((size_t)bh*SS + krow)*32 + kk2b;
    const size_t vgo = ((size_t)bh*1024 + vkp)*64 + vdb;

    {
        const int row = tid >> 1, cb = (tid & 1) * 16;
        const uint32_t* sh = qh_g + ((size_t)bh*SS + qi*128 + row)*32 + cb;
        const uint32_t* sl = ql_g + ((size_t)bh*SS + qi*128 + row)*32 + cb;
        uint32_t dh = sbase + (row*QP + cb)*4;
        uint32_t dl = sbase + (4608 + row*QP + cb)*4;
        CPA16(dh,    sh);     CPA16(dh+16, sh+4);
        CPA16(dh+32, sh+8);   CPA16(dh+48, sh+12);
        CPA16(dl,    sl);     CPA16(dl+16, sl+4);
        CPA16(dl+32, sl+8);   CPA16(dl+48, sl+12);
    }
    CPA_COMMIT();

    #pragma unroll
    for (int pk = 0; pk < 2; pk++) {
        uint32_t kh_d = sbase + (9216  + pk*2304 + krow*QP + kk2b)*4;
        uint32_t kl_d = sbase + (13824 + pk*2304 + krow*QP + kk2b)*4;
        uint32_t vh_d = sbase + (18432 + pk*2304 + vkp*VP + vdb)*4;
        uint32_t vl_d = sbase + (23040 + pk*2304 + vkp*VP + vdb)*4;
        const uint32_t* skh = kh_g + kgo + (size_t)pk*64*32;
        const uint32_t* skl = kl_g + kgo + (size_t)pk*64*32;
        const uint32_t* svh = vh_g + vgo + (size_t)pk*32*64;
        const uint32_t* svl = vl_g + vgo + (size_t)pk*32*64;
        CPA16(kh_d, skh);  CPA16(kh_d+16, skh+4);
        CPA16(kl_d, skl);  CPA16(kl_d+16, skl+4);
        CPA16(vh_d, svh);  CPA16(vh_d+16, svh+4);
        CPA16(vl_d, svl);  CPA16(vl_d+16, svl+4);
        CPA_COMMIT();
    }

    float l0 = 0.f, l1 = 0.f;
    float of[8][4];
    #pragma unroll
    for (int nt = 0; nt < 8; nt++)
        #pragma unroll
        for (int i = 0; i < 4; i++) of[nt][i] = 0.f;

    const uint32_t* QhS = smu;
    const uint32_t* QlS = smu + 4608;

    for (int kt = 0; kt < nkt; kt++) {
        const int st = kt & 1;
        if (kt + 1 < nkt) { CPA_WAIT(1); } else { CPA_WAIT(0); }
        __syncthreads();

        const uint32_t* KhS = smu + 9216  + st*2304;
        const uint32_t* KlS = smu + 13824 + st*2304;
        const uint32_t* VhS = smu + 18432 + st*2304;
        const uint32_t* VlS = smu + 23040 + st*2304;

        // ---- S = Q K^T (pass-major MMA emission) ----
        float sf[8][4];
        #pragma unroll
        for (int nt = 0; nt < 8; nt++)
            #pragma unroll
            for (int i = 0; i < 4; i++) sf[nt][i] = 0.f;

        #pragma unroll
        for (int kc = 0; kc < 4; kc++) {
            uint32_t ah[4], al[4];
            const int k2a = qk + 8*kc, k2c = k2a + 4;
            const int r0o = (wr + qrow)*QP, r1o = (wr + qrow + 8)*QP;
            ah[0] = QhS[r0o + k2a]; ah[1] = QhS[r1o + k2a];
            ah[2] = QhS[r0o + k2c]; ah[3] = QhS[r1o + k2c];
            al[0] = QlS[r0o + k2a]; al[1] = QlS[r1o + k2a];
            al[2] = QlS[r0o + k2c]; al[3] = QlS[r1o + k2c];
            // pass 1: ah x Kh
            #pragma unroll
            for (int nt = 0; nt < 8; nt++) {
                const int co = (nt*8 + qrow)*QP;
                uint32_t bb[2] = { KhS[co + k2a], KhS[co + k2c] };
                MMA_BF16(sf[nt], ah, bb);
            }
            // pass 2: ah x Kl
            #pragma unroll
            for (int nt = 0; nt < 8; nt++) {
                const int co = (nt*8 + qrow)*QP;
                uint32_t bb[2] = { KlS[co + k2a], KlS[co + k2c] };
                MMA_BF16(sf[nt], ah, bb);
            }
            // pass 3: al x Kh
            #pragma unroll
            for (int nt = 0; nt < 8; nt++) {
                const int co = (nt*8 + qrow)*QP;
                uint32_t bb[2] = { KhS[co + k2a], KhS[co + k2c] };
                MMA_BF16(sf[nt], al, bb);
            }
        }

        if (kt >= 2*qi) {
            #pragma unroll
            for (int nt = 0; nt < 8; nt++) {
                #pragma unroll
                for (int i = 0; i < 4; i++) {
                    int col_g = kt*64 + nt*8 + 2*qk + (i & 1);
                    int row_g = qi*128 + wr + qrow + 8*(i >> 1);
                    if (col_g > row_g) sf[nt][i] = -1e30f;
                }
            }
        }

        #pragma unroll
        for (int nt = 0; nt < 8; nt++) {
            sf[nt][0] = ex2(sf[nt][0]);
            sf[nt][1] = ex2(sf[nt][1]);
            sf[nt][2] = ex2(sf[nt][2]);
            sf[nt][3] = ex2(sf[nt][3]);
            l0 += sf[nt][0] + sf[nt][1];
            l1 += sf[nt][2] + sf[nt][3];
        }

        // ---- O += P V (pass-major MMA emission) ----
        #pragma unroll
        for (int kc = 0; kc < 4; kc++) {
            uint32_t pah[4], pal[4];
            float r0, r1;
            pah[0] = pack_hi(sf[2*kc][0],   sf[2*kc][1],   r0, r1); pal[0] = pack_lo(r0, r1);
            pah[1] = pack_hi(sf[2*kc][2],   sf[2*kc][3],   r0, r1); pal[1] = pack_lo(r0, r1);
            pah[2] = pack_hi(sf[2*kc+1][0], sf[2*kc+1][1], r0, r1); pal[2] = pack_lo(r0, r1);
            pah[3] = pack_hi(sf[2*kc+1][2], sf[2*kc+1][3], r0, r1); pal[3] = pack_lo(r0, r1);
            const int kpa = 8*kc + qk, kpc = kpa + 4;
            // pass 1: pah x Vh
            #pragma unroll
            for (int nt = 0; nt < 8; nt++) {
                const int col = nt*8 + qrow;
                uint32_t bb[2] = { VhS[kpa*VP + col], VhS[kpc*VP + col] };
                MMA_BF16(of[nt], pah, bb);
            }
            // pass 2: pah x Vl
            #pragma unroll
            for (int nt = 0; nt < 8; nt++) {
                const int col = nt*8 + qrow;
                uint32_t bb[2] = { VlS[kpa*VP + col], VlS[kpc*VP + col] };
                MMA_BF16(of[nt], pah, bb);
            }
            // pass 3: pal x Vh
            #pragma unroll
            for (int nt = 0; nt < 8; nt++) {
                const int col = nt*8 + qrow;
                uint32_t bb[2] = { VhS[kpa*VP + col], VhS[kpc*VP + col] };
                MMA_BF16(of[nt], pal, bb);
            }
        }

        __syncthreads();

        if (kt + 2 < nkt) {
            const int nk = kt + 2;
            uint32_t kh_d = sbase + (9216  + st*2304 + krow*QP + kk2b)*4;
            uint32_t kl_d = sbase + (13824 + st*2304 + krow*QP + kk2b)*4;
            uint32_t vh_d = sbase + (18432 + st*2304 + vkp*VP + vdb)*4;
            uint32_t vl_d = sbase + (23040 + st*2304 + vkp*VP + vdb)*4;
            const uint32_t* skh = kh_g + kgo + (size_t)nk*64*32;
            const uint32_t* skl = kl_g + kgo + (size_t)nk*64*32;
            const uint32_t* svh = vh_g + vgo + (size_t)nk*32*64;
            const uint32_t* svl = vl_g + vgo + (size_t)nk*32*64;
            CPA16(kh_d, skh);  CPA16(kh_d+16, skh+4);
            CPA16(kl_d, skl);  CPA16(kl_d+16, skl+4);
            CPA16(vh_d, svh);  CPA16(vh_d+16, svh+4);
            CPA16(vl_d, svl);  CPA16(vl_d+16, svl+4);
            CPA_COMMIT();
        }
    }

    l0 += __shfl_xor_sync(0xffffffffu, l0, 1);
    l0 += __shfl_xor_sync(0xffffffffu, l0, 2);
    l1 += __shfl_xor_sync(0xffffffffu, l1, 1);
    l1 += __shfl_xor_sync(0xffffffffu, l1, 2);

    float inv0 = 1.f / l0, inv1 = 1.f / l1;
    #pragma unroll
    for (int nt = 0; nt < 8; nt++) {
        const int k2g = h*32 + nt*4 + qk;
        const int row0 = b*SS + qi*128 + wr + qrow;
        float r0, r1;
        uint32_t hv = pack_hi(of[nt][0]*inv0, of[nt][1]*inv0, r0, r1);
        cth[(size_t)row0*512 + k2g] = hv;
        ctl[(size_t)row0*512 + k2g] = pack_lo(r0, r1);
        hv = pack_hi(of[nt][2]*inv1, of[nt][3]*inv1, r0, r1);
        cth[(size_t)(row0+8)*512 + k2g] = hv;
        ctl[(size_t)(row0+8)*512 + k2g] = pack_lo(r0, r1);
    }
}

// ---------------------------------------------------------------------------
extern "C" void kernel_launch(void* const* d_in, const int* in_sizes, int n_in,
                              void* d_out, int out_size)
{
    (void)in_sizes; (void)n_in; (void)out_size;
    const float* query = (const float*)d_in[0];
    const float* key   = (const float*)d_in[1];
    const float* value = (const float*)d_in[2];
    const float* Wq = (const float*)d_in[4];
    const float* bq = (const float*)d_in[5];
    const float* Wk = (const float*)d_in[6];
    const float* bk = (const float*)d_in[7];
    const float* Wv = (const float*)d_in[8];
    const float* bv = (const float*)d_in[9];
    const float* Wo = (const float*)d_in[10];
    const float* bo = (const float*)d_in[11];
    float* out = (float*)d_out;

    float *qlin, *klin, *vlin, *cosT, *sinT;
    uint32_t *qh, *ql, *kh, *kl, *vh, *vl;
    uint32_t *ah, *al, *wh, *wl, *cth, *ctl;
    cudaGetSymbolAddress((void**)&qlin, g_qlin);
    cudaGetSymbolAddress((void**)&klin, g_klin);
    cudaGetSymbolAddress((void**)&vlin, g_vlin);
    cudaGetSymbolAddress((void**)&cosT, g_cos);
    cudaGetSymbolAddress((void**)&sinT, g_sin);
    cudaGetSymbolAddress((void**)&qh, g_qh);
    cudaGetSymbolAddress((void**)&ql, g_ql);
    cudaGetSymbolAddress((void**)&kh, g_kh);
    cudaGetSymbolAddress((void**)&kl, g_kl);
    cudaGetSymbolAddress((void**)&vh, g_vh);
    cudaGetSymbolAddress((void**)&vl, g_vl);
    cudaGetSymbolAddress((void**)&ah, g_ah);
    cudaGetSymbolAddress((void**)&al, g_al);
    cudaGetSymbolAddress((void**)&wh, g_wh);
    cudaGetSymbolAddress((void**)&wl, g_wl);
    cudaGetSymbolAddress((void**)&cth, g_cth);
    cudaGetSymbolAddress((void**)&ctl, g_ctl);

    const size_t ASTRIDE = (size_t)MROWS*512;
    const size_t WSTRIDE = (size_t)DD*512;

    cudaFuncSetAttribute(flash_tc5, cudaFuncAttributeMaxDynamicSharedMemorySize, FLASH_SMEM);

    rope_tables<<<SS*32/256, 256>>>(cosT, sinT);

    const int ABLK = MROWS*DD/8/256;   // 2048
    const int WBLK = DD*DD/8/256;      // 512
    dim3 sp3Grid(ABLK, 3);
    split_pack3<<<sp3Grid, 256>>>(query, key, value, ah, al, ASTRIDE);
    dim3 sp4Grid(WBLK, 4);
    split_pack4<<<sp4Grid, 256>>>(Wq, Wk, Wv, Wo, wh, wl, WSTRIDE);

    GArg gq = { ah + 0*ASTRIDE, al + 0*ASTRIDE, wh + 0*WSTRIDE, wl + 0*WSTRIDE, bq, qlin };
    GArg gk = { ah + 1*ASTRIDE, al + 1*ASTRIDE, wh + 1*WSTRIDE, wl + 1*WSTRIDE, bk, klin };
    GArg gv = { ah + 2*ASTRIDE, al + 2*ASTRIDE, wh + 2*WSTRIDE, wl + 2*WSTRIDE, bv, vlin };
    dim3 gemmGrid(DD/128, MROWS/128, 3);
    gemm_tc2<<<gemmGrid, 256>>>(gq, gk, gv);

    dim3 rsGrid((BB*HH*SS*16)/256, 2);
    rope_split<<<rsGrid, 256>>>(qlin, klin, cosT, sinT, qh, ql, kh, kl);
    v_split<<<(BB*HH*1024*16)/256, 256>>>(vlin, vh, vl);

    dim3 faGrid(SS/128, BB*HH);            // (16, 32)
    flash_tc5<<<faGrid, 256, FLASH_SMEM>>>(qh, ql, kh, kl, vh, vl, cth, ctl);

    GArg go = { cth, ctl, wh + 3*WSTRIDE, wl + 3*WSTRIDE, bo, out };
    dim3 gemmGridO(DD/128, MROWS/128, 1);
    gemm_tc2<<<gemmGridO, 256>>>(go, go, go);
}

// round 12
// speedup vs baseline: 1.2851x; 1.1530x over previous
#include <cuda_runtime.h>
#include <cuda_bf16.h>
#include <math.h>
#include <stdint.h>

#define BB 2
#define SS 2048
#define DD 1024
#define HH 16
#define DK 64
#define MROWS (BB*SS)   // 4096

// Scratch (device globals — allocation is forbidden)
__device__ float g_qlin[MROWS*DD];
__device__ float g_klin[MROWS*DD];
__device__ float g_vlin[MROWS*DD];
__device__ float g_cos[SS*32];
__device__ float g_sin[SS*32];
// bf16-split packed operands for flash: u32 = packed bf16x2
__device__ uint32_t g_qh[BB*HH*SS*32];
__device__ uint32_t g_ql[BB*HH*SS*32];
__device__ uint32_t g_kh[BB*HH*SS*32];
__device__ uint32_t g_kl[BB*HH*SS*32];
__device__ uint32_t g_vh[BB*HH*(SS/2)*DK];
__device__ uint32_t g_vl[BB*HH*(SS/2)*DK];
// bf16-split packed GEMM operands, CHUNK-MAJOR blocked: [chunk64][rows][8 u32]
__device__ uint32_t g_ah[3][MROWS*512];
__device__ uint32_t g_al[3][MROWS*512];
__device__ uint32_t g_wh[4][DD*512];
__device__ uint32_t g_wl[4][DD*512];
__device__ uint32_t g_cth[MROWS*512];
__device__ uint32_t g_ctl[MROWS*512];

// ---------------------------------------------------------------------------
__device__ __forceinline__ uint32_t pack_hi(float a, float b, float& ra, float& rb)
{
    __nv_bfloat16 ha = __float2bfloat16(a);
    __nv_bfloat16 hb = __float2bfloat16(b);
    ra = a - __bfloat162float(ha);
    rb = b - __bfloat162float(hb);
    __nv_bfloat162 p;
    p.x = ha; p.y = hb;
    return *reinterpret_cast<uint32_t*>(&p);
}
__device__ __forceinline__ uint32_t pack_lo(float ra, float rb)
{
    __nv_bfloat162 p = __floats2bfloat162_rn(ra, rb);
    return *reinterpret_cast<uint32_t*>(&p);
}
__device__ __forceinline__ float ex2(float x)
{
    float r;
    asm("ex2.approx.f32 %0, %1;" : "=f"(r) : "f"(x));
    return r;
}

#define MMA_BF16(d, a, b) \
    asm volatile("mma.sync.aligned.m16n8k16.row.col.f32.bf16.bf16.f32 " \
        "{%0,%1,%2,%3}, {%4,%5,%6,%7}, {%8,%9}, {%0,%1,%2,%3};" \
        : "+f"(d[0]), "+f"(d[1]), "+f"(d[2]), "+f"(d[3]) \
        : "r"(a[0]), "r"(a[1]), "r"(a[2]), "r"(a[3]), "r"(b[0]), "r"(b[1]))

#define CPA16(dst, src)  asm volatile("cp.async.cg.shared.global [%0], [%1], 16;" :: "r"(dst), "l"(src))
#define CPA_COMMIT()     asm volatile("cp.async.commit_group;" ::: "memory")
#define CPA_WAIT(N)      asm volatile("cp.async.wait_group %0;" :: "n"(N) : "memory")

// ---------------------------------------------------------------------------
__global__ __launch_bounds__(256) void rope_tables(float* cosT, float* sinT)
{
    const int t = blockIdx.x * 256 + threadIdx.x;
    const int j = t & 31;
    const int s = t >> 5;
    double inv = exp(-(double)j * 0.28782313662425575);
    double sd, cd;
    sincos((double)s * inv, &sd, &cd);
    cosT[t] = (float)cd;
    sinT[t] = (float)sd;
}

// ---------------------------------------------------------------------------
// split_pack to CHUNK-MAJOR blocked layout: dst[(chunk*nrows + row)*8 + half*4]
// (chunk = 16-col group; reads stay coalesced, writes are 32B segments).
// ---------------------------------------------------------------------------
__global__ __launch_bounds__(256) void split_pack3(
    const float* __restrict__ X0, const float* __restrict__ X1,
    const float* __restrict__ X2,
    uint32_t* __restrict__ Xh, uint32_t* __restrict__ Xl, size_t ostride)
{
    const float* X = (blockIdx.y == 0) ? X0 : ((blockIdx.y == 1) ? X1 : X2);
    uint32_t* H = Xh + blockIdx.y * ostride;
    uint32_t* L = Xl + blockIdx.y * ostride;
    const size_t t = (size_t)blockIdx.x * 256 + threadIdx.x;
    const int row   = (int)(t >> 7);        // 128 groups of 8 floats per row
    const int rem   = (int)(t & 127);
    const int chunk = rem >> 1;
    const int half  = rem & 1;
    float4 v0 = ((const float4*)X)[2*t];
    float4 v1 = ((const float4*)X)[2*t+1];
    float r0, r1, r2, r3, r4, r5, r6, r7;
    uint4 h, l;
    h.x = pack_hi(v0.x, v0.y, r0, r1);
    h.y = pack_hi(v0.z, v0.w, r2, r3);
    h.z = pack_hi(v1.x, v1.y, r4, r5);
    h.w = pack_hi(v1.z, v1.w, r6, r7);
    l.x = pack_lo(r0, r1); l.y = pack_lo(r2, r3);
    l.z = pack_lo(r4, r5); l.w = pack_lo(r6, r7);
    const size_t d = ((size_t)chunk * MROWS + row) * 2 + half;   // uint4 units
    ((uint4*)H)[d] = h;
    ((uint4*)L)[d] = l;
}

__global__ __launch_bounds__(256) void split_pack4(
    const float* __restrict__ X0, const float* __restrict__ X1,
    const float* __restrict__ X2, const float* __restrict__ X3,
    uint32_t* __restrict__ Xh, uint32_t* __restrict__ Xl, size_t ostride)
{
    const float* X = (blockIdx.y == 0) ? X0 : ((blockIdx.y == 1) ? X1 :
                     ((blockIdx.y == 2) ? X2 : X3));
    uint32_t* H = Xh + blockIdx.y * ostride;
    uint32_t* L = Xl + blockIdx.y * ostride;
    const size_t t = (size_t)blockIdx.x * 256 + threadIdx.x;
    const int row   = (int)(t >> 7);
    const int rem   = (int)(t & 127);
    const int chunk = rem >> 1;
    const int half  = rem & 1;
    float4 v0 = ((const float4*)X)[2*t];
    float4 v1 = ((const float4*)X)[2*t+1];
    float r0, r1, r2, r3, r4, r5, r6, r7;
    uint4 h, l;
    h.x = pack_hi(v0.x, v0.y, r0, r1);
    h.y = pack_hi(v0.z, v0.w, r2, r3);
    h.z = pack_hi(v1.x, v1.y, r4, r5);
    h.w = pack_hi(v1.z, v1.w, r6, r7);
    l.x = pack_lo(r0, r1); l.y = pack_lo(r2, r3);
    l.z = pack_lo(r4, r5); l.w = pack_lo(r6, r7);
    const size_t d = ((size_t)chunk * DD + row) * 2 + half;      // uint4 units
    ((uint4*)H)[d] = h;
    ((uint4*)L)[d] = l;
}

// ---------------------------------------------------------------------------
// Tensor-core GEMM from pre-split bf16 hi/lo, double-buffered LDG path.
// Operands are CHUNK-MAJOR blocked: per iteration each array's tile slice is
// one contiguous 4KB block -> warp LDG.128 = 4 wavefronts (was ~16).
// A arrays have MROWS rows (chunk stride 32768 u32); W arrays DD rows (8192).
// ---------------------------------------------------------------------------
#define GP 136
#define ACH 32768   // u32 per chunk in activation arrays (4096 rows * 8)
#define WCH 8192    // u32 per chunk in weight arrays (1024 rows * 8)

struct GArg {
    const uint32_t *ah, *al, *wh, *wl;
    const float* bias;
    float* c;
};

__global__ __launch_bounds__(256, 2) void gemm_tc2(GArg g0, GArg g1, GArg g2)
{
    GArg g = (blockIdx.z == 0) ? g0 : ((blockIdx.z == 1) ? g1 : g2);
    __shared__ uint32_t Ah[2][8][GP], Al[2][8][GP], Wh[2][8][GP], Wl[2][8][GP];

    const int tid = threadIdx.x;
    const int bm = blockIdx.y, bn = blockIdx.x;
    const int lane = tid & 31, wid = tid >> 5;
    const int wm = (wid >> 2) * 64;
    const int wn = (wid & 3) * 32;
    const int qrow = lane >> 2, qk = lane & 3;

    const int r = tid >> 1;
    const int k2b = (tid & 1) * 4;

    // chunk-0 base pointers (add c*ACH / c*WCH per chunk)
    const uint32_t* AhG = g.ah + ((size_t)(bm*128 + r))*8 + k2b;
    const uint32_t* AlG = g.al + ((size_t)(bm*128 + r))*8 + k2b;
    const uint32_t* WhG = g.wh + ((size_t)(bn*128 + r))*8 + k2b;
    const uint32_t* WlG = g.wl + ((size_t)(bn*128 + r))*8 + k2b;

    float d[4][4][4];
    #pragma unroll
    for (int mt = 0; mt < 4; mt++)
        #pragma unroll
        for (int nt = 0; nt < 4; nt++)
            #pragma unroll
            for (int i = 0; i < 4; i++) d[mt][nt][i] = 0.f;

    {
        uint4 a = *(const uint4*)AhG;
        uint4 b = *(const uint4*)AlG;
        uint4 c = *(const uint4*)WhG;
        uint4 e = *(const uint4*)WlG;
        Ah[0][k2b+0][r] = a.x; Ah[0][k2b+1][r] = a.y; Ah[0][k2b+2][r] = a.z; Ah[0][k2b+3][r] = a.w;
        Al[0][k2b+0][r] = b.x; Al[0][k2b+1][r] = b.y; Al[0][k2b+2][r] = b.z; Al[0][k2b+3][r] = b.w;
        Wh[0][k2b+0][r] = c.x; Wh[0][k2b+1][r] = c.y; Wh[0][k2b+2][r] = c.z; Wh[0][k2b+3][r] = c.w;
        Wl[0][k2b+0][r] = e.x; Wl[0][k2b+1][r] = e.y; Wl[0][k2b+2][r] = e.z; Wl[0][k2b+3][r] = e.w;
    }
    __syncthreads();

    int st = 0;
    for (int c = 1; c <= 64; c++) {
        uint4 na, nb, nc, ne;
        const bool has = (c < 64);
        if (has) {
            na = *(const uint4*)(AhG + (size_t)c*ACH);
            nb = *(const uint4*)(AlG + (size_t)c*ACH);
            nc = *(const uint4*)(WhG + (size_t)c*WCH);
            ne = *(const uint4*)(WlG + (size_t)c*WCH);
        }

        uint32_t afh[4][4], afl[4][4], bfh[4][2], bfl[4][2];
        #pragma unroll
        for (int mt = 0; mt < 4; mt++) {
            int m0 = wm + mt*16 + qrow;
            #pragma unroll
            for (int i = 0; i < 4; i++) {
                int m  = m0 + ((i & 1) << 3);
                int k2 = qk + ((i >> 1) << 2);
                afh[mt][i] = Ah[st][k2][m];
                afl[mt][i] = Al[st][k2][m];
            }
        }
        #pragma unroll
        for (int nt = 0; nt < 4; nt++) {
            int n0 = wn + nt*8 + qrow;
            #pragma unroll
            for (int i = 0; i < 2; i++) {
                bfh[nt][i] = Wh[st][qk + 4*i][n0];
                bfl[nt][i] = Wl[st][qk + 4*i][n0];
            }
        }

        #pragma unroll
        for (int mt = 0; mt < 4; mt++)
            #pragma unroll
            for (int nt = 0; nt < 4; nt++) {
                MMA_BF16(d[mt][nt], afh[mt], bfh[nt]);
                MMA_BF16(d[mt][nt], afh[mt], bfl[nt]);
                MMA_BF16(d[mt][nt], afl[mt], bfh[nt]);
            }

        if (has) {
            int s2 = st ^ 1;
            Ah[s2][k2b+0][r] = na.x; Ah[s2][k2b+1][r] = na.y; Ah[s2][k2b+2][r] = na.z; Ah[s2][k2b+3][r] = na.w;
            Al[s2][k2b+0][r] = nb.x; Al[s2][k2b+1][r] = nb.y; Al[s2][k2b+2][r] = nb.z; Al[s2][k2b+3][r] = nb.w;
            Wh[s2][k2b+0][r] = nc.x; Wh[s2][k2b+1][r] = nc.y; Wh[s2][k2b+2][r] = nc.z; Wh[s2][k2b+3][r] = nc.w;
            Wl[s2][k2b+0][r] = ne.x; Wl[s2][k2b+1][r] = ne.y; Wl[s2][k2b+2][r] = ne.z; Wl[s2][k2b+3][r] = ne.w;
        }
        __syncthreads();
        st ^= 1;
    }

    #pragma unroll
    for (int mt = 0; mt < 4; mt++)
        #pragma unroll
        for (int nt = 0; nt < 4; nt++) {
            int col0 = bn*128 + wn + nt*8 + 2*qk;
            float b0 = g.bias[col0], b1 = g.bias[col0+1];
            #pragma unroll
            for (int half = 0; half < 2; half++) {
                int row = bm*128 + wm + mt*16 + qrow + 8*half;
                float2 v;
                v.x = d[mt][nt][2*half+0] + b0;
                v.y = d[mt][nt][2*half+1] + b1;
                *(float2*)&g.c[(size_t)row*DD + col0] = v;
            }
        }
}

// ---------------------------------------------------------------------------
// RoPE + head-transpose + bf16 split for Q,K. Q scale = (1/8)*log2(e).
// ---------------------------------------------------------------------------
__global__ __launch_bounds__(256) void rope_split(
    const float* __restrict__ qlin, const float* __restrict__ klin,
    const float* __restrict__ cosT, const float* __restrict__ sinT,
    uint32_t* __restrict__ qh, uint32_t* __restrict__ ql,
    uint32_t* __restrict__ kh, uint32_t* __restrict__ kl)
{
    const int t = blockIdx.x * 256 + threadIdx.x;
    const float* src = blockIdx.y ? klin : qlin;
    uint32_t* dh = blockIdx.y ? kh : qh;
    uint32_t* dl = blockIdx.y ? kl : ql;
    const float scale = blockIdx.y ? 1.0f : 0.18033688011112042f;  // 0.125*log2(e)

    const int k2 = t & 15;
    const int s  = (t >> 4) & (SS - 1);
    const int bh = t >> 15;
    const int b = bh >> 4, h = bh & 15;
    const int j0 = 2*k2, j1 = 2*k2 + 1;

    const float* sp = src + ((size_t)(b*SS + s))*DD + h*DK;
    float x0 = sp[j0],      x1 = sp[j1];
    float y0 = sp[j0 + 32], y1 = sp[j1 + 32];
    float c0 = cosT[s*32 + j0], c1 = cosT[s*32 + j1];
    float s0 = sinT[s*32 + j0], s1 = sinT[s*32 + j1];

    float o0 = (x0*c0 - y0*s0) * scale;
    float o1 = (x1*c1 - y1*s1) * scale;
    float p0 = (y0*c0 + x0*s0) * scale;
    float p1 = (y1*c1 + x1*s1) * scale;

    size_t base = ((size_t)bh*SS + s)*32;
    float r0, r1;
    uint32_t hv = pack_hi(o0, o1, r0, r1);
    dh[base + k2] = hv;            dl[base + k2] = pack_lo(r0, r1);
    hv = pack_hi(p0, p1, r0, r1);
    dh[base + k2 + 16] = hv;       dl[base + k2 + 16] = pack_lo(r0, r1);
}

// ---------------------------------------------------------------------------
__global__ __launch_bounds__(256) void v_split(
    const float* __restrict__ vlin,
    uint32_t* __restrict__ vh, uint32_t* __restrict__ vl)
{
    const int t = blockIdx.x * 256 + threadIdx.x;
    const int d4 = (t & 15) * 4;
    const int kp = (t >> 4) & 1023;
    const int bh = t >> 14;
    const int b = bh >> 4, h = bh & 15;

    const float* r0p = vlin + ((size_t)(b*SS + 2*kp))*DD + h*DK + d4;
    float4 a = *(const float4*)r0p;
    float4 c = *(const float4*)(r0p + DD);

    uint32_t hh[4], ll[4];
    float ra, rb;
    hh[0] = pack_hi(a.x, c.x, ra, rb); ll[0] = pack_lo(ra, rb);
    hh[1] = pack_hi(a.y, c.y, ra, rb); ll[1] = pack_lo(ra, rb);
    hh[2] = pack_hi(a.z, c.z, ra, rb); ll[2] = pack_lo(ra, rb);
    hh[3] = pack_hi(a.w, c.w, ra, rb); ll[3] = pack_lo(ra, rb);

    size_t base = ((size_t)bh*1024 + kp)*64 + d4;
    *(uint4*)&vh[base] = make_uint4(hh[0], hh[1], hh[2], hh[3]);
    *(uint4*)&vl[base] = make_uint4(ll[0], ll[1], ll[2], ll[3]);
}

// ---------------------------------------------------------------------------
// Flash v5: no-max softmax, cp.async double-buffered K/V, pass-major MMAs.
// Epilogue writes packed bf16 ctx in CHUNK-MAJOR blocked layout for gemm Wo.
// ---------------------------------------------------------------------------
#define QP 36
#define VP 72
#define FLASH_SMEM (27648*4)

__global__ __launch_bounds__(256, 2) void flash_tc5(
    const uint32_t* __restrict__ qh_g, const uint32_t* __restrict__ ql_g,
    const uint32_t* __restrict__ kh_g, const uint32_t* __restrict__ kl_g,
    const uint32_t* __restrict__ vh_g, const uint32_t* __restrict__ vl_g,
    uint32_t* __restrict__ cth, uint32_t* __restrict__ ctl)
{
    extern __shared__ uint32_t smu[];
    const uint32_t sbase = (uint32_t)__cvta_generic_to_shared(smu);

    const int tid = threadIdx.x;
    const int qi = 15 - blockIdx.x;
    const int bh = blockIdx.y;
    const int b = bh >> 4, h = bh & 15;
    const int lane = tid & 31, wid = tid >> 5;
    const int qk = lane & 3, qrow = lane >> 2;
    const int wr = wid * 16;
    const int nkt = 2*qi + 2;

    const int krow = tid >> 2, kk2b = (tid & 3) * 8;
    const int vkp  = tid >> 3, vdb  = (tid & 7) * 8;
    const size_t kgo = ((size_t)bh*SS + krow)*32 + kk2b;
    const size_t vgo = ((size_t)bh*1024 + vkp)*64 + vdb;

    {
        const int row = tid >> 1, cb = (tid & 1) * 16;
        const uint32_t* sh = qh_g + ((size_t)bh*SS + qi*128 + row)*32 + cb;
        const uint32_t* sl = ql_g + ((size_t)bh*SS + qi*128 + row)*32 + cb;
        uint32_t dh = sbase + (row*QP + cb)*4;
        uint32_t dl = sbase + (4608 + row*QP + cb)*4;
        CPA16(dh,    sh);     CPA16(dh+16, sh+4);
        CPA16(dh+32, sh+8);   CPA16(dh+48, sh+12);
        CPA16(dl,    sl);     CPA16(dl+16, sl+4);
        CPA16(dl+32, sl+8);   CPA16(dl+48, sl+12);
    }
    CPA_COMMIT();

    #pragma unroll
    for (int pk = 0; pk < 2; pk++) {
        uint32_t kh_d = sbase + (9216  + pk*2304 + krow*QP + kk2b)*4;
        uint32_t kl_d = sbase + (13824 + pk*2304 + krow*QP + kk2b)*4;
        uint32_t vh_d = sbase + (18432 + pk*2304 + vkp*VP + vdb)*4;
        uint32_t vl_d = sbase + (23040 + pk*2304 + vkp*VP + vdb)*4;
        const uint32_t* skh = kh_g + kgo + (size_t)pk*64*32;
        const uint32_t* skl = kl_g + kgo + (size_t)pk*64*32;
        const uint32_t* svh = vh_g + vgo + (size_t)pk*32*64;
        const uint32_t* svl = vl_g + vgo + (size_t)pk*32*64;
        CPA16(kh_d, skh);  CPA16(kh_d+16, skh+4);
        CPA16(kl_d, skl);  CPA16(kl_d+16, skl+4);
        CPA16(vh_d, svh);  CPA16(vh_d+16, svh+4);
        CPA16(vl_d, svl);  CPA16(vl_d+16, svl+4);
        CPA_COMMIT();
    }

    float l0 = 0.f, l1 = 0.f;
    float of[8][4];
    #pragma unroll
    for (int nt = 0; nt < 8; nt++)
        #pragma unroll
        for (int i = 0; i < 4; i++) of[nt][i] = 0.f;

    const uint32_t* QhS = smu;
    const uint32_t* QlS = smu + 4608;

    for (int kt = 0; kt < nkt; kt++) {
        const int st = kt & 1;
        if (kt + 1 < nkt) { CPA_WAIT(1); } else { CPA_WAIT(0); }
        __syncthreads();

        const uint32_t* KhS = smu + 9216  + st*2304;
        const uint32_t* KlS = smu + 13824 + st*2304;
        const uint32_t* VhS = smu + 18432 + st*2304;
        const uint32_t* VlS = smu + 23040 + st*2304;

        float sf[8][4];
        #pragma unroll
        for (int nt = 0; nt < 8; nt++)
            #pragma unroll
            for (int i = 0; i < 4; i++) sf[nt][i] = 0.f;

        #pragma unroll
        for (int kc = 0; kc < 4; kc++) {
            uint32_t ah[4], al[4];
            const int k2a = qk + 8*kc, k2c = k2a + 4;
            const int r0o = (wr + qrow)*QP, r1o = (wr + qrow + 8)*QP;
            ah[0] = QhS[r0o + k2a]; ah[1] = QhS[r1o + k2a];
            ah[2] = QhS[r0o + k2c]; ah[3] = QhS[r1o + k2c];
            al[0] = QlS[r0o + k2a]; al[1] = QlS[r1o + k2a];
            al[2] = QlS[r0o + k2c]; al[3] = QlS[r1o + k2c];
            #pragma unroll
            for (int nt = 0; nt < 8; nt++) {
                const int co = (nt*8 + qrow)*QP;
                uint32_t bb[2] = { KhS[co + k2a], KhS[co + k2c] };
                MMA_BF16(sf[nt], ah, bb);
            }
            #pragma unroll
            for (int nt = 0; nt < 8; nt++) {
                const int co = (nt*8 + qrow)*QP;
                uint32_t bb[2] = { KlS[co + k2a], KlS[co + k2c] };
                MMA_BF16(sf[nt], ah, bb);
            }
            #pragma unroll
            for (int nt = 0; nt < 8; nt++) {
                const int co = (nt*8 + qrow)*QP;
                uint32_t bb[2] = { KhS[co + k2a], KhS[co + k2c] };
                MMA_BF16(sf[nt], al, bb);
            }
        }

        if (kt >= 2*qi) {
            #pragma unroll
            for (int nt = 0; nt < 8; nt++) {
                #pragma unroll
                for (int i = 0; i < 4; i++) {
                    int col_g = kt*64 + nt*8 + 2*qk + (i & 1);
                    int row_g = qi*128 + wr + qrow + 8*(i >> 1);
                    if (col_g > row_g) sf[nt][i] = -1e30f;
                }
            }
        }

        #pragma unroll
        for (int nt = 0; nt < 8; nt++) {
            sf[nt][0] = ex2(sf[nt][0]);
            sf[nt][1] = ex2(sf[nt][1]);
            sf[nt][2] = ex2(sf[nt][2]);
            sf[nt][3] = ex2(sf[nt][3]);
            l0 += sf[nt][0] + sf[nt][1];
            l1 += sf[nt][2] + sf[nt][3];
        }

        #pragma unroll
        for (int kc = 0; kc < 4; kc++) {
            uint32_t pah[4], pal[4];
            float r0, r1;
            pah[0] = pack_hi(sf[2*kc][0],   sf[2*kc][1],   r0, r1); pal[0] = pack_lo(r0, r1);
            pah[1] = pack_hi(sf[2*kc][2],   sf[2*kc][3],   r0, r1); pal[1] = pack_lo(r0, r1);
            pah[2] = pack_hi(sf[2*kc+1][0], sf[2*kc+1][1], r0, r1); pal[2] = pack_lo(r0, r1);
            pah[3] = pack_hi(sf[2*kc+1][2], sf[2*kc+1][3], r0, r1); pal[3] = pack_lo(r0, r1);
            const int kpa = 8*kc + qk, kpc = kpa + 4;
            #pragma unroll
            for (int nt = 0; nt < 8; nt++) {
                const int col = nt*8 + qrow;
                uint32_t bb[2] = { VhS[kpa*VP + col], VhS[kpc*VP + col] };
                MMA_BF16(of[nt], pah, bb);
            }
            #pragma unroll
            for (int nt = 0; nt < 8; nt++) {
                const int col = nt*8 + qrow;
                uint32_t bb[2] = { VlS[kpa*VP + col], VlS[kpc*VP + col] };
                MMA_BF16(of[nt], pah, bb);
            }
            #pragma unroll
            for (int nt = 0; nt < 8; nt++) {
                const int col = nt*8 + qrow;
                uint32_t bb[2] = { VhS[kpa*VP + col], VhS[kpc*VP + col] };
                MMA_BF16(of[nt], pal, bb);
            }
        }

        __syncthreads();

        if (kt + 2 < nkt) {
            const int nk = kt + 2;
            uint32_t kh_d = sbase + (9216  + st*2304 + krow*QP + kk2b)*4;
            uint32_t kl_d = sbase + (13824 + st*2304 + krow*QP + kk2b)*4;
            uint32_t vh_d = sbase + (18432 + st*2304 + vkp*VP + vdb)*4;
            uint32_t vl_d = sbase + (23040 + st*2304 + vkp*VP + vdb)*4;
            const uint32_t* skh = kh_g + kgo + (size_t)nk*64*32;
            const uint32_t* skl = kl_g + kgo + (size_t)nk*64*32;
            const uint32_t* svh = vh_g + vgo + (size_t)nk*32*64;
            const uint32_t* svl = vl_g + vgo + (size_t)nk*32*64;
            CPA16(kh_d, skh);  CPA16(kh_d+16, skh+4);
            CPA16(kl_d, skl);  CPA16(kl_d+16, skl+4);
            CPA16(vh_d, svh);  CPA16(vh_d+16, svh+4);
            CPA16(vl_d, svl);  CPA16(vl_d+16, svl+4);
            CPA_COMMIT();
        }
    }

    l0 += __shfl_xor_sync(0xffffffffu, l0, 1);
    l0 += __shfl_xor_sync(0xffffffffu, l0, 2);
    l1 += __shfl_xor_sync(0xffffffffu, l1, 1);
    l1 += __shfl_xor_sync(0xffffffffu, l1, 2);

    float inv0 = 1.f / l0, inv1 = 1.f / l1;
    #pragma unroll
    for (int nt = 0; nt < 8; nt++) {
        const int k2g = h*32 + nt*4 + qk;
        const int chn = k2g >> 3, wix = k2g & 7;
        const int row0 = b*SS + qi*128 + wr + qrow;
        float r0, r1;
        uint32_t hv = pack_hi(of[nt][0]*inv0, of[nt][1]*inv0, r0, r1);
        size_t di = ((size_t)chn*MROWS + row0)*8 + wix;
        cth[di] = hv;
        ctl[di] = pack_lo(r0, r1);
        hv = pack_hi(of[nt][2]*inv1, of[nt][3]*inv1, r0, r1);
        di = ((size_t)chn*MROWS + row0 + 8)*8 + wix;
        cth[di] = hv;
        ctl[di] = pack_lo(r0, r1);
    }
}

// ---------------------------------------------------------------------------
extern "C" void kernel_launch(void* const* d_in, const int* in_sizes, int n_in,
                              void* d_out, int out_size)
{
    (void)in_sizes; (void)n_in; (void)out_size;
    const float* query = (const float*)d_in[0];
    const float* key   = (const float*)d_in[1];
    const float* value = (const float*)d_in[2];
    const float* Wq = (const float*)d_in[4];
    const float* bq = (const float*)d_in[5];
    const float* Wk = (const float*)d_in[6];
    const float* bk = (const float*)d_in[7];
    const float* Wv = (const float*)d_in[8];
    const float* bv = (const float*)d_in[9];
    const float* Wo = (const float*)d_in[10];
    const float* bo = (const float*)d_in[11];
    float* out = (float*)d_out;

    float *qlin, *klin, *vlin, *cosT, *sinT;
    uint32_t *qh, *ql, *kh, *kl, *vh, *vl;
    uint32_t *ah, *al, *wh, *wl, *cth, *ctl;
    cudaGetSymbolAddress((void**)&qlin, g_qlin);
    cudaGetSymbolAddress((void**)&klin, g_klin);
    cudaGetSymbolAddress((void**)&vlin, g_vlin);
    cudaGetSymbolAddress((void**)&cosT, g_cos);
    cudaGetSymbolAddress((void**)&sinT, g_sin);
    cudaGetSymbolAddress((void**)&qh, g_qh);
    cudaGetSymbolAddress((void**)&ql, g_ql);
    cudaGetSymbolAddress((void**)&kh, g_kh);
    cudaGetSymbolAddress((void**)&kl, g_kl);
    cudaGetSymbolAddress((void**)&vh, g_vh);
    cudaGetSymbolAddress((void**)&vl, g_vl);
    cudaGetSymbolAddress((void**)&ah, g_ah);
    cudaGetSymbolAddress((void**)&al, g_al);
    cudaGetSymbolAddress((void**)&wh, g_wh);
    cudaGetSymbolAddress((void**)&wl, g_wl);
    cudaGetSymbolAddress((void**)&cth, g_cth);
    cudaGetSymbolAddress((void**)&ctl, g_ctl);

    const size_t ASTRIDE = (size_t)MROWS*512;
    const size_t WSTRIDE = (size_t)DD*512;

    cudaFuncSetAttribute(flash_tc5, cudaFuncAttributeMaxDynamicSharedMemorySize, FLASH_SMEM);

    rope_tables<<<SS*32/256, 256>>>(cosT, sinT);

    const int ABLK = MROWS*DD/8/256;   // 2048
    const int WBLK = DD*DD/8/256;      // 512
    dim3 sp3Grid(ABLK, 3);
    split_pack3<<<sp3Grid, 256>>>(query, key, value, ah, al, ASTRIDE);
    dim3 sp4Grid(WBLK, 4);
    split_pack4<<<sp4Grid, 256>>>(Wq, Wk, Wv, Wo, wh, wl, WSTRIDE);

    GArg gq = { ah + 0*ASTRIDE, al + 0*ASTRIDE, wh + 0*WSTRIDE, wl + 0*WSTRIDE, bq, qlin };
    GArg gk = { ah + 1*ASTRIDE, al + 1*ASTRIDE, wh + 1*WSTRIDE, wl + 1*WSTRIDE, bk, klin };
    GArg gv = { ah + 2*ASTRIDE, al + 2*ASTRIDE, wh + 2*WSTRIDE, wl + 2*WSTRIDE, bv, vlin };
    dim3 gemmGrid(DD/128, MROWS/128, 3);
    gemm_tc2<<<gemmGrid, 256>>>(gq, gk, gv);

    dim3 rsGrid((BB*HH*SS*16)/256, 2);
    rope_split<<<rsGrid, 256>>>(qlin, klin, cosT, sinT, qh, ql, kh, kl);
    v_split<<<(BB*HH*1024*16)/256, 256>>>(vlin, vh, vl);

    dim3 faGrid(SS/128, BB*HH);            // (16, 32)
    flash_tc5<<<faGrid, 256, FLASH_SMEM>>>(qh, ql, kh, kl, vh, vl, cth, ctl);

    GArg go = { cth, ctl, wh + 3*WSTRIDE, wl + 3*WSTRIDE, bo, out };
    dim3 gemmGridO(DD/128, MROWS/128, 1);
    gemm_tc2<<<gemmGridO, 256>>>(go, go, go);
}